// round 7
// baseline (speedup 1.0000x reference)
#include <cuda_runtime.h>
#include <math.h>
#include <stdint.h>

// ---------------- problem constants ----------------
#define DIM_    1024
#define ED_     512
#define NE_     8192
#define NROWS_  4096            // B*CODES
#define K2_     4608            // ED*9
#define NSPL_   64              // distance N-tiles (8192/128)

// Output packing (float32 concat):
// out [64,64,1024] | perplexity [1] | codebooks_used [8192] | min_indices [4096]
#define OFF_PERP  4194304
#define OFF_CB    4194305
#define OFF_IDX   4202497

// ---------------- scratch (static device globals) ----------------
__device__ float g_Y[16384 * ED_];                  // proj output [16384,512]
__device__ float g_col[(size_t)NROWS_ * K2_];       // im2col [4096,4608] (k' = kk*512+c)
__device__ float g_Wc[ED_ * K2_];                   // conv_w reordered [512][kk*512+c]
__device__ float g_x[NROWS_ * ED_];                 // encoder diff x [4096,512]
__device__ float g_Aq[NROWS_ * ED_];                // quantized, scrambled for decode
__device__ float g_WinT[ED_ * DIM_];                // W_in^T  [512,1024]
__device__ float g_WoutT[DIM_ * ED_];               // W_out^T [1024,512]
__device__ float g_cnorm[NE_];
__device__ unsigned long long g_part[NROWS_ * NSPL_];
__device__ int g_minidx[NROWS_];
__device__ int g_counts[NE_];

// ---------------- helpers ----------------
__device__ __forceinline__ uint32_t tf32_rna(float f) {
    uint32_t u; asm("cvt.rna.tf32.f32 %0, %1;" : "=r"(u) : "f"(f)); return u;
}
__device__ __forceinline__ void mma_tf32(float* c, const uint32_t* a, uint32_t b0, uint32_t b1) {
    asm volatile(
        "mma.sync.aligned.m16n8k8.row.col.f32.tf32.tf32.f32 "
        "{%0,%1,%2,%3}, {%4,%5,%6,%7}, {%8,%9}, {%0,%1,%2,%3};"
        : "+f"(c[0]), "+f"(c[1]), "+f"(c[2]), "+f"(c[3])
        : "r"(a[0]), "r"(a[1]), "r"(a[2]), "r"(a[3]), "r"(b0), "r"(b1));
}

// Fragment-packed smem, per stage (u32 offsets):
//   A_hi [0,4096)  A_lo [4096,8192)  B_hi [8192,12288)  B_lo [12288,16384)
// A slot: ((mb*4+ks)*32 + lane)*4 + (2*hi4 + half)   mb=row>>4
// B slot: ((nb*4+ks)*32 + lane)*2 + hi4              nb=n>>3
#define STAGE_U  16384
#define SMEM_BYTES (2 * STAGE_U * 4 + 2048)

// ---------------- 3xTF32 emulated-fp32 GEMM via mma.sync ----------------
// C[M,N] = A @ Bt^T; A [M,K] row-major, Bt [N,K] row-major. CTA tile 128x128, Kc=32.
// AMODE 0: A = A0 - A1.  EPI 0: store C.  EPI 1: C + bias[n].  EPI 2: argmin(cn[n]-2*acc).
template <int AMODE, int EPI>
__global__ void __launch_bounds__(256, 1) mm_gemm(
    const float* __restrict__ A0, const float* __restrict__ A1,
    const float* __restrict__ Bt, const float* __restrict__ bias,
    const float* __restrict__ cn, float* __restrict__ C,
    unsigned long long* __restrict__ part,
    int K, int lda, int ldb, int ldc)
{
    extern __shared__ __align__(16) uint32_t smem[];
    const int tid  = threadIdx.x;
    const int wid  = tid >> 5;
    const int lane = tid & 31;
    const int g    = lane >> 2;     // 0..7
    const int t    = lane & 3;      // 0..3
    const int wm   = wid & 3;       // 4 warps along M (32 rows each)
    const int wn   = wid >> 2;      // 2 warps along N (64 cols each)
    const int m0   = blockIdx.y * 128;
    const int n0   = blockIdx.x * 128;

    // producer-thread constants
    const int drA   = (tid >> 3) & 3;
    const int rowA0 = 16 * (wid >> 2) + 8 * (drA >> 1) + 2 * (wid & 3) + (drA & 1); // +32i
    const int rowB0 = tid >> 3;                                                     // +32i
    const int c4    = (tid & 7) << 2;
    const int ksP   = (tid >> 1) & 3;
    const int hi4P  = tid & 1;
    const int mbA0  = rowA0 >> 4;           // +2i
    const int gA    = rowA0 & 7;
    const int halfA = (rowA0 >> 3) & 1;
    const int nbB0  = rowB0 >> 3;           // +4i
    const int gB    = rowB0 & 7;

    float acc[2][8][4];
#pragma unroll
    for (int mf = 0; mf < 2; ++mf)
#pragma unroll
        for (int nf = 0; nf < 8; ++nf)
#pragma unroll
            for (int q = 0; q < 4; ++q) acc[mf][nf][q] = 0.f;

    const int NC = K >> 5;
    float4 pa[4], pb[4];

    auto g2r = [&](int k0) {
#pragma unroll
        for (int i = 0; i < 4; ++i) {
            const int rA = rowA0 + 32 * i;
            pa[i] = *(const float4*)(A0 + (size_t)(m0 + rA) * lda + k0 + c4);
            if (AMODE == 0) {
                const float4 u = *(const float4*)(A1 + (size_t)(m0 + rA) * lda + k0 + c4);
                pa[i].x -= u.x; pa[i].y -= u.y; pa[i].z -= u.z; pa[i].w -= u.w;
            }
            const int rB = rowB0 + 32 * i;
            pb[i] = *(const float4*)(Bt + (size_t)(n0 + rB) * ldb + k0 + c4);
        }
    };

    auto r2s = [&](int stage) {
        uint32_t* sAh = smem + stage * STAGE_U;
        uint32_t* sAl = sAh + 4096;
        uint32_t* sBh = sAh + 8192;
        uint32_t* sBl = sAh + 12288;
#pragma unroll
        for (int i = 0; i < 4; ++i) {
            const float va0 = pa[i].x, va1 = pa[i].y, va2 = pa[i].z, va3 = pa[i].w;
            const float vb0 = pb[i].x, vb1 = pb[i].y, vb2 = pb[i].z, vb3 = pb[i].w;
            const int mb = mbA0 + 2 * i;
            const int nb = nbB0 + 4 * i;
            const uint32_t abase = (uint32_t)(((mb * 4 + ksP) * 32 + gA * 4) * 4 + 2 * hi4P + halfA);
            const uint32_t bbase = (uint32_t)(((nb * 4 + ksP) * 32 + gB * 4) * 2 + hi4P);
#pragma unroll
            for (int j = 0; j < 4; ++j) {
                const int tt = (j + ksP) & 3;       // staggered -> conflict-free STS
                const float va = tt == 0 ? va0 : tt == 1 ? va1 : tt == 2 ? va2 : va3;
                const float vb = tt == 0 ? vb0 : tt == 1 ? vb1 : tt == 2 ? vb2 : vb3;
                const uint32_t ha = tf32_rna(va);
                sAh[abase + tt * 4] = ha;
                sAl[abase + tt * 4] = tf32_rna(va - __uint_as_float(ha));
                const uint32_t hb = tf32_rna(vb);
                sBh[bbase + tt * 2] = hb;
                sBl[bbase + tt * 2] = tf32_rna(vb - __uint_as_float(hb));
            }
        }
    };

    auto compute = [&](int stage) {
        const uint32_t* sm = smem + stage * STAGE_U;
#pragma unroll
        for (int ks = 0; ks < 4; ++ks) {
            uint4 ah[2], al[2];
#pragma unroll
            for (int mf = 0; mf < 2; ++mf) {
                const int idx = (((wm * 2 + mf) * 4 + ks) * 32 + lane) * 4;
                ah[mf] = *(const uint4*)(sm + idx);
                al[mf] = *(const uint4*)(sm + 4096 + idx);
            }
#pragma unroll
            for (int nf = 0; nf < 8; ++nf) {
                const int bidx = (((wn * 8 + nf) * 4 + ks) * 32 + lane) * 2;
                const uint2 bh = *(const uint2*)(sm + 8192 + bidx);
                const uint2 bl = *(const uint2*)(sm + 12288 + bidx);
#pragma unroll
                for (int mf = 0; mf < 2; ++mf) {
                    mma_tf32(acc[mf][nf], (const uint32_t*)&ah[mf], bh.x, bh.y);
                    mma_tf32(acc[mf][nf], (const uint32_t*)&ah[mf], bl.x, bl.y);
                    mma_tf32(acc[mf][nf], (const uint32_t*)&al[mf], bh.x, bh.y);
                }
            }
        }
    };

    g2r(0);
    r2s(0);
    __syncthreads();

    for (int c = 0; c < NC; ++c) {
        if (c + 1 < NC) g2r((c + 1) << 5);
        compute(c & 1);
        if (c + 1 < NC) r2s((c + 1) & 1);
        __syncthreads();
    }

    // ---- epilogue ----
    // acc[mf][nf][q]: row = m0 + wm*32 + mf*16 + g + (q>=2 ? 8 : 0)
    //                 col = n0 + wn*64 + nf*8 + 2t + (q&1)
    if (EPI == 0 || EPI == 1) {
#pragma unroll
        for (int mf = 0; mf < 2; ++mf) {
#pragma unroll
            for (int half = 0; half < 2; ++half) {
                const int row = m0 + wm * 32 + mf * 16 + g + half * 8;
                float* crow = C + (size_t)row * ldc + n0 + wn * 64;
#pragma unroll
                for (int nf = 0; nf < 8; ++nf) {
                    const int colb = nf * 8 + 2 * t;
                    float2 v;
                    v.x = acc[mf][nf][half * 2 + 0];
                    v.y = acc[mf][nf][half * 2 + 1];
                    if (EPI == 1) {
                        v.x += bias[n0 + wn * 64 + colb];
                        v.y += bias[n0 + wn * 64 + colb + 1];
                    }
                    *(float2*)(crow + colb) = v;
                }
            }
        }
    } else {
        unsigned long long* red = (unsigned long long*)(smem + 2 * STAGE_U); // [128][2]
#pragma unroll
        for (int mf = 0; mf < 2; ++mf) {
#pragma unroll
            for (int half = 0; half < 2; ++half) {
                float best = __int_as_float(0x7f800000);
                int bi = 0;
#pragma unroll
                for (int nf = 0; nf < 8; ++nf) {
#pragma unroll
                    for (int q = 0; q < 2; ++q) {
                        const int n = n0 + wn * 64 + nf * 8 + 2 * t + q;
                        const float v = cn[n] - 2.f * acc[mf][nf][half * 2 + q];
                        if (v < best) { best = v; bi = n; }
                    }
                }
                unsigned fu = __float_as_uint(best);
                fu = (fu & 0x80000000u) ? ~fu : (fu | 0x80000000u);
                unsigned long long packed = ((unsigned long long)fu << 32) | (unsigned)bi;
#pragma unroll
                for (int off = 1; off < 4; off <<= 1) {
                    unsigned long long o = __shfl_xor_sync(0xffffffffu, packed, off);
                    if (o < packed) packed = o;
                }
                if (t == 0) {
                    const int rl = wm * 32 + mf * 16 + g + half * 8;
                    red[rl * 2 + wn] = packed;
                }
            }
        }
        __syncthreads();
        if (tid < 128) {
            unsigned long long a = red[tid * 2], b = red[tid * 2 + 1];
            part[(size_t)(m0 + tid) * NSPL_ + blockIdx.x] = (a < b) ? a : b;
        }
    }
}

// ---------------- small kernels ----------------
__global__ void transpose_k(const float* __restrict__ src, float* __restrict__ dst, int R, int C)
{
    int e = blockIdx.x * 256 + threadIdx.x;
    if (e >= R * C) return;
    int rr = e / C, cc = e - rr * C;
    dst[(size_t)cc * R + rr] = src[e];
}

// conv_w [O][C][3][3] -> g_Wc [O][kk*512 + c]
__global__ void reorder_w(const float* __restrict__ cw, float* __restrict__ wc)
{
    int e = blockIdx.x * 256 + threadIdx.x;
    if (e >= ED_ * K2_) return;
    int o = e / K2_;
    int r = e - o * K2_;
    int kk = r >> 9;
    int c = r & 511;
    wc[e] = cw[(size_t)o * K2_ + c * 9 + kk];
}

// g_Y [B,256,512] -> g_col [4096][kk*512 + c]   (coalesced read & write)
__global__ void im2col_k(float* __restrict__ col)
{
    int e = blockIdx.x * 256 + threadIdx.x;
    if (e >= NROWS_ * K2_) return;
    int rr = e / K2_;
    int k2 = e - rr * K2_;
    int kk = k2 >> 9;
    int c = k2 & 511;
    int ky = kk / 3;
    int kx = kk - ky * 3;
    int b = rr >> 6, p = rr & 63;
    int h = p >> 3, w = p & 7;
    int gy = 2 * h - 1 + ky;
    int gx = 2 * w - 1 + kx;
    float v = 0.f;
    if ((unsigned)gy < 16u && (unsigned)gx < 16u)
        v = g_Y[(size_t)(b * 256 + gy * 16 + gx) * ED_ + c];
    col[e] = v;
}

__global__ void cnorm_k(const float* __restrict__ Cb, float* __restrict__ cnp)
{
    int rr = blockIdx.x * 8 + (threadIdx.x >> 5);
    int lane = threadIdx.x & 31;
    const float* p = Cb + (size_t)rr * ED_;
    float s = 0.f;
    for (int i = lane; i < ED_; i += 32) { float v = p[i]; s = fmaf(v, v, s); }
#pragma unroll
    for (int off = 16; off > 0; off >>= 1) s += __shfl_down_sync(0xffffffffu, s, off);
    if (lane == 0) cnp[rr] = s;
}

__global__ void reduce_argmin(float* __restrict__ outIdxF, int writeIdx)
{
    int n = blockIdx.x * 256 + threadIdx.x;
    if (n >= NROWS_) return;
    unsigned long long best = ~0ull;
#pragma unroll 8
    for (int s = 0; s < NSPL_; ++s) {
        unsigned long long v = g_part[(size_t)n * NSPL_ + s];
        if (v < best) best = v;
    }
    int idx = (int)(unsigned)(best & 0xFFFFFFFFull);
    g_minidx[n] = idx;
    atomicAdd(&g_counts[idx], 1);
    if (writeIdx) outIdxF[n] = (float)idx;
}

// quantized = x + (||x-hard||/||rand|| + eps)*rand, written in decode-scrambled layout
__global__ void noise_k(const float* __restrict__ Cb, const float* __restrict__ rv)
{
    const int n = blockIdx.x;            // n = b*64 + p
    const int tid = threadIdx.x;         // 128 threads
    const int idx = g_minidx[n];
    const int b = n >> 6, p = n & 63;
    const float* xr = g_x + (size_t)n * ED_;
    const float* hr = Cb + (size_t)idx * ED_;
    const float* rr = rv + (size_t)n * ED_;

    float s1 = 0.f, s2 = 0.f;
    for (int i = tid; i < ED_; i += 128) {
        float d = xr[i] - hr[i];
        s1 = fmaf(d, d, s1);
        float rrr = rr[i];
        s2 = fmaf(rrr, rrr, s2);
    }
#pragma unroll
    for (int off = 16; off > 0; off >>= 1) {
        s1 += __shfl_down_sync(0xffffffffu, s1, off);
        s2 += __shfl_down_sync(0xffffffffu, s2, off);
    }
    __shared__ float sh1[4], sh2[4];
    int wid = tid >> 5, lane = tid & 31;
    if (lane == 0) { sh1[wid] = s1; sh2[wid] = s2; }
    __syncthreads();
    float t1 = sh1[0] + sh1[1] + sh1[2] + sh1[3];
    float t2 = sh2[0] + sh2[1] + sh2[2] + sh2[3];
    float scale = sqrtf(t1) / sqrtf(t2) + 1e-12f;
    for (int i = tid; i < ED_; i += 128) {
        float q = fmaf(scale, rr[i], xr[i]);
        // scrambled target: row m = b*64 + (i&63), col k = p*8 + (i>>6)
        g_Aq[(size_t)(b * 64 + (i & 63)) * ED_ + p * 8 + (i >> 6)] = q;
    }
}

__global__ void stats_k(float* __restrict__ d_out, int out_size)
{
    __shared__ float red[256];
    int tid = threadIdx.x;
    float s = 0.f;
    for (int i = tid; i < NE_; i += 256) {
        float c = (float)g_counts[i];
        float p = c * (1.f / (float)NROWS_);
        s += p * logf(p + 1e-12f);
        if (out_size > OFF_CB + i) d_out[OFF_CB + i] = c;
    }
    red[tid] = s;
    __syncthreads();
    for (int st = 128; st > 0; st >>= 1) {
        if (tid < st) red[tid] += red[tid + st];
        __syncthreads();
    }
    if (tid == 0 && out_size > OFF_PERP) d_out[OFF_PERP] = expf(-red[0]);
}

// ---------------- host launcher ----------------
extern "C" void kernel_launch(void* const* d_in, const int* in_sizes, int n_in,
                              void* d_out, int out_size)
{
    const float* first = (const float*)d_in[0];
    const float* last = (const float*)d_in[1];
    const float* W_in = (const float*)d_in[2];
    const float* conv_w = (const float*)d_in[4];
    const float* W_out = (const float*)d_in[6];
    const float* b_out = (const float*)d_in[7];
    const float* codebooks = (const float*)d_in[8];
    const float* randv = (const float*)d_in[9];
    float* out = (float*)d_out;

    float *pY, *pCol, *pWc, *pX, *pAq, *pWinT, *pWoutT, *pCn;
    unsigned long long* pPart;
    int* pCnt;
    cudaGetSymbolAddress((void**)&pY, g_Y);
    cudaGetSymbolAddress((void**)&pCol, g_col);
    cudaGetSymbolAddress((void**)&pWc, g_Wc);
    cudaGetSymbolAddress((void**)&pX, g_x);
    cudaGetSymbolAddress((void**)&pAq, g_Aq);
    cudaGetSymbolAddress((void**)&pWinT, g_WinT);
    cudaGetSymbolAddress((void**)&pWoutT, g_WoutT);
    cudaGetSymbolAddress((void**)&pCn, g_cnorm);
    cudaGetSymbolAddress((void**)&pPart, g_part);
    cudaGetSymbolAddress((void**)&pCnt, g_counts);

    cudaFuncSetAttribute(mm_gemm<0, 0>, cudaFuncAttributeMaxDynamicSharedMemorySize, SMEM_BYTES);
    cudaFuncSetAttribute(mm_gemm<1, 0>, cudaFuncAttributeMaxDynamicSharedMemorySize, SMEM_BYTES);
    cudaFuncSetAttribute(mm_gemm<1, 1>, cudaFuncAttributeMaxDynamicSharedMemorySize, SMEM_BYTES);
    cudaFuncSetAttribute(mm_gemm<1, 2>, cudaFuncAttributeMaxDynamicSharedMemorySize, SMEM_BYTES);

    cudaMemsetAsync(pCnt, 0, NE_ * sizeof(int));

    // weight preps
    transpose_k<<<(DIM_ * ED_ + 255) / 256, 256>>>(W_in, pWinT, DIM_, ED_);
    transpose_k<<<(ED_ * DIM_ + 255) / 256, 256>>>(W_out, pWoutT, ED_, DIM_);
    reorder_w<<<(ED_ * K2_ + 255) / 256, 256>>>(conv_w, pWc);

    // 1. projection: (last-first)[16384,1024] @ W_in -> g_Y [16384,512]
    mm_gemm<0, 0><<<dim3(4, 128), 256, SMEM_BYTES>>>(
        last, first, pWinT, nullptr, nullptr, pY, nullptr, DIM_, DIM_, DIM_, ED_);
    // 2. im2col
    im2col_k<<<((size_t)NROWS_ * K2_ + 255) / 256, 256>>>(pCol);
    // 3. conv GEMM: col [4096,4608] @ g_Wc^T -> g_x [4096,512]
    mm_gemm<1, 0><<<dim3(4, 32), 256, SMEM_BYTES>>>(
        pCol, nullptr, pWc, nullptr, nullptr, pX, nullptr, K2_, K2_, K2_, ED_);
    // 4. codebook norms
    cnorm_k<<<NE_ / 8, 256>>>(codebooks, pCn);
    // 5. distance GEMM + fused argmin partials
    mm_gemm<1, 2><<<dim3(NSPL_, 32), 256, SMEM_BYTES>>>(
        pX, nullptr, codebooks, nullptr, pCn, nullptr, pPart, ED_, ED_, ED_, 0);
    // 6. reduce + histogram + min_indices
    int writeIdx = (out_size >= OFF_IDX + NROWS_) ? 1 : 0;
    reduce_argmin<<<NROWS_ / 256, 256>>>(out + OFF_IDX, writeIdx);
    // 7. noise substitution -> scrambled g_Aq
    noise_k<<<NROWS_, 128>>>(codebooks, randv);
    // 8. decode: g_Aq [4096,512] @ W_out + b_out -> out [4096,1024]
    mm_gemm<1, 1><<<dim3(8, 32), 256, SMEM_BYTES>>>(
        pAq, nullptr, pWoutT, b_out, nullptr, out, nullptr, ED_, ED_, ED_, DIM_);
    // 9. perplexity + codebooks_used
    stats_k<<<1, 256>>>(out, out_size);
}

// round 9
// speedup vs baseline: 1.1133x; 1.1133x over previous
#include <cuda_runtime.h>
#include <math.h>
#include <stdint.h>

// ---------------- problem constants ----------------
#define DIM_    1024
#define ED_     512
#define NE_     8192
#define NROWS_  4096            // B*CODES
#define K2_     4608            // ED*9
#define NSPL_   64              // distance N-tiles (8192/128)

// Output packing (float32 concat):
// out [64,64,1024] | perplexity [1] | codebooks_used [8192] | min_indices [4096]
#define OFF_PERP  4194304
#define OFF_CB    4194305
#define OFF_IDX   4202497

// ---------------- scratch (static device globals) ----------------
__device__ float g_Y[16384 * ED_];                  // proj output [16384,512]
__device__ float g_col[(size_t)NROWS_ * K2_];       // im2col [4096,4608] (k' = kk*512+c)
__device__ float g_Wc[ED_ * K2_];                   // conv_w reordered [512][kk*512+c]
__device__ float g_xs[2 * NROWS_ * ED_];            // conv split-K partial outputs
__device__ float g_x[NROWS_ * ED_];                 // encoder diff x [4096,512]
__device__ float g_Aq[NROWS_ * ED_];                // quantized, scrambled for decode
__device__ float g_WinT[ED_ * DIM_];                // W_in^T  [512,1024]
__device__ float g_WoutT[DIM_ * ED_];               // W_out^T [1024,512]
__device__ float g_cnorm[NE_];
__device__ unsigned long long g_part[NROWS_ * NSPL_];
__device__ int g_minidx[NROWS_];
__device__ int g_counts[NE_];

// ---------------- helpers ----------------
__device__ __forceinline__ uint32_t tf32_rna(float f) {
    uint32_t u; asm("cvt.rna.tf32.f32 %0, %1;" : "=r"(u) : "f"(f)); return u;
}
__device__ __forceinline__ void mma_tf32(float* c, const uint32_t* a, uint32_t b0, uint32_t b1) {
    asm volatile(
        "mma.sync.aligned.m16n8k8.row.col.f32.tf32.tf32.f32 "
        "{%0,%1,%2,%3}, {%4,%5,%6,%7}, {%8,%9}, {%0,%1,%2,%3};"
        : "+f"(c[0]), "+f"(c[1]), "+f"(c[2]), "+f"(c[3])
        : "r"(a[0]), "r"(a[1]), "r"(a[2]), "r"(a[3]), "r"(b0), "r"(b1));
}

// Fragment-packed fp32 staging, per stage (float offsets):
//   A [0,4096)  B [4096,8192)
// A slot: ((mb*4+ks)*32 + lane)*4 + (2*hi4 + half)   mb=row>>4
// B slot: ((nb*4+ks)*32 + lane)*2 + hi4              nb=n>>3
#define STAGE_F  8192
#define SMEM_BYTES (2 * STAGE_F * 4 + 2048)

// ---------------- 3xTF32 emulated-fp32 GEMM via mma.sync ----------------
// C[M,N] = A @ Bt^T; A [M,K] row-major, Bt [N,K] row-major. CTA tile 128x128, Kc=32.
// grid.z = split-K: block z uses A/Bt column offset z*K and writes C + z*czoff.
// AMODE 0: A = A0 - A1.  EPI 0: store C.  EPI 1: C + bias[n].  EPI 2: argmin(cn[n]-2*acc).
template <int AMODE, int EPI>
__global__ void __launch_bounds__(256, 2) mm_gemm(
    const float* __restrict__ A0, const float* __restrict__ A1,
    const float* __restrict__ Bt, const float* __restrict__ bias,
    const float* __restrict__ cn, float* __restrict__ C,
    unsigned long long* __restrict__ part,
    int K, int lda, int ldb, int ldc, size_t czoff)
{
    extern __shared__ __align__(16) float smemf[];
    const int tid  = threadIdx.x;
    const int wid  = tid >> 5;
    const int lane = tid & 31;
    const int g    = lane >> 2;     // 0..7
    const int t    = lane & 3;      // 0..3
    const int wm   = wid & 3;       // 4 warps along M (32 rows each)
    const int wn   = wid >> 2;      // 2 warps along N (64 cols each)
    const int m0   = blockIdx.y * 128;
    const int n0   = blockIdx.x * 128;

    // split-K offsets
    const int zz = blockIdx.z;
    A0 += (size_t)zz * K;
    if (AMODE == 0) A1 += (size_t)zz * K;
    Bt += (size_t)zz * K;
    C  += (size_t)zz * czoff;

    // producer-thread constants (verified conflict-free mapping)
    const int drA   = (tid >> 3) & 3;
    const int rowA0 = 16 * (wid >> 2) + 8 * (drA >> 1) + 2 * (wid & 3) + (drA & 1); // +32i
    const int rowB0 = tid >> 3;                                                     // +32i
    const int c4    = (tid & 7) << 2;       // = 8*ksP + 4*hi4P
    const int ksP   = (tid >> 1) & 3;
    const int hi4P  = tid & 1;
    const int mbA0  = rowA0 >> 4;           // +2i
    const int gA    = rowA0 & 7;
    const int halfA = (rowA0 >> 3) & 1;
    const int nbB0  = rowB0 >> 3;           // +4i
    const int gB    = rowB0 & 7;

    float acc[2][8][4];
#pragma unroll
    for (int mf = 0; mf < 2; ++mf)
#pragma unroll
        for (int nf = 0; nf < 8; ++nf)
#pragma unroll
            for (int q = 0; q < 4; ++q) acc[mf][nf][q] = 0.f;

    const int NC = K >> 5;
    float4 pa[4], pb[4];

    auto g2r = [&](int k0) {
#pragma unroll
        for (int i = 0; i < 4; ++i) {
            const int rA = rowA0 + 32 * i;
            pa[i] = *(const float4*)(A0 + (size_t)(m0 + rA) * lda + k0 + c4);
            if (AMODE == 0) {
                const float4 u = *(const float4*)(A1 + (size_t)(m0 + rA) * lda + k0 + c4);
                pa[i].x -= u.x; pa[i].y -= u.y; pa[i].z -= u.z; pa[i].w -= u.w;
            }
            const int rB = rowB0 + 32 * i;
            pb[i] = *(const float4*)(Bt + (size_t)(n0 + rB) * ldb + k0 + c4);
        }
    };

    auto r2s = [&](int stage) {
        float* sA = smemf + stage * STAGE_F;
        float* sB = sA + 4096;
#pragma unroll
        for (int i = 0; i < 4; ++i) {
            const float va0 = pa[i].x, va1 = pa[i].y, va2 = pa[i].z, va3 = pa[i].w;
            const float vb0 = pb[i].x, vb1 = pb[i].y, vb2 = pb[i].z, vb3 = pb[i].w;
            const int mb = mbA0 + 2 * i;
            const int nb = nbB0 + 4 * i;
            const uint32_t abase = (uint32_t)(((mb * 4 + ksP) * 32 + gA * 4) * 4 + 2 * hi4P + halfA);
            const uint32_t bbase = (uint32_t)(((nb * 4 + ksP) * 32 + gB * 4) * 2 + hi4P);
#pragma unroll
            for (int j = 0; j < 4; ++j) {
                const int tt = (j + ksP) & 3;       // staggered -> conflict-free STS
                const float va = tt == 0 ? va0 : tt == 1 ? va1 : tt == 2 ? va2 : va3;
                const float vb = tt == 0 ? vb0 : tt == 1 ? vb1 : tt == 2 ? vb2 : vb3;
                sA[abase + tt * 4] = va;
                sB[bbase + tt * 2] = vb;
            }
        }
    };

    auto compute = [&](int stage) {
        const float* sA = smemf + stage * STAGE_F;
        const float* sB = sA + 4096;
#pragma unroll
        for (int ks = 0; ks < 4; ++ks) {
            uint32_t ah[2][4], al[2][4];
#pragma unroll
            for (int mf = 0; mf < 2; ++mf) {
                const float4 af = *(const float4*)(sA + (((wm * 2 + mf) * 4 + ks) * 32 + lane) * 4);
                const float a0 = af.x, a1 = af.y, a2 = af.z, a3 = af.w;
                ah[mf][0] = tf32_rna(a0); al[mf][0] = tf32_rna(a0 - __uint_as_float(ah[mf][0]));
                ah[mf][1] = tf32_rna(a1); al[mf][1] = tf32_rna(a1 - __uint_as_float(ah[mf][1]));
                ah[mf][2] = tf32_rna(a2); al[mf][2] = tf32_rna(a2 - __uint_as_float(ah[mf][2]));
                ah[mf][3] = tf32_rna(a3); al[mf][3] = tf32_rna(a3 - __uint_as_float(ah[mf][3]));
            }
#pragma unroll
            for (int nf = 0; nf < 8; ++nf) {
                const float2 bf = *(const float2*)(sB + (((wn * 8 + nf) * 4 + ks) * 32 + lane) * 2);
                const uint32_t bh0 = tf32_rna(bf.x);
                const uint32_t bh1 = tf32_rna(bf.y);
                const uint32_t bl0 = tf32_rna(bf.x - __uint_as_float(bh0));
                const uint32_t bl1 = tf32_rna(bf.y - __uint_as_float(bh1));
#pragma unroll
                for (int mf = 0; mf < 2; ++mf) {
                    mma_tf32(acc[mf][nf], ah[mf], bh0, bh1);
                    mma_tf32(acc[mf][nf], ah[mf], bl0, bl1);
                    mma_tf32(acc[mf][nf], al[mf], bh0, bh1);
                }
            }
        }
    };

    g2r(0);
    r2s(0);
    __syncthreads();

    for (int c = 0; c < NC; ++c) {
        if (c + 1 < NC) g2r((c + 1) << 5);
        compute(c & 1);
        if (c + 1 < NC) r2s((c + 1) & 1);
        __syncthreads();
    }

    // ---- epilogue ----
    // acc[mf][nf][q]: row = m0 + wm*32 + mf*16 + g + (q>=2 ? 8 : 0)
    //                 col = n0 + wn*64 + nf*8 + 2t + (q&1)
    if (EPI == 0 || EPI == 1) {
#pragma unroll
        for (int mf = 0; mf < 2; ++mf) {
#pragma unroll
            for (int half = 0; half < 2; ++half) {
                const int row = m0 + wm * 32 + mf * 16 + g + half * 8;
                float* crow = C + (size_t)row * ldc + n0 + wn * 64;
#pragma unroll
                for (int nf = 0; nf < 8; ++nf) {
                    const int colb = nf * 8 + 2 * t;
                    float2 v;
                    v.x = acc[mf][nf][half * 2 + 0];
                    v.y = acc[mf][nf][half * 2 + 1];
                    if (EPI == 1) {
                        v.x += bias[n0 + wn * 64 + colb];
                        v.y += bias[n0 + wn * 64 + colb + 1];
                    }
                    *(float2*)(crow + colb) = v;
                }
            }
        }
    } else {
        unsigned long long* red = (unsigned long long*)(smemf + 2 * STAGE_F); // [128][2]
#pragma unroll
        for (int mf = 0; mf < 2; ++mf) {
#pragma unroll
            for (int half = 0; half < 2; ++half) {
                float best = __int_as_float(0x7f800000);
                int bi = 0;
#pragma unroll
                for (int nf = 0; nf < 8; ++nf) {
#pragma unroll
                    for (int q = 0; q < 2; ++q) {
                        const int n = n0 + wn * 64 + nf * 8 + 2 * t + q;
                        const float v = cn[n] - 2.f * acc[mf][nf][half * 2 + q];
                        if (v < best) { best = v; bi = n; }
                    }
                }
                unsigned fu = __float_as_uint(best);
                fu = (fu & 0x80000000u) ? ~fu : (fu | 0x80000000u);
                unsigned long long packed = ((unsigned long long)fu << 32) | (unsigned)bi;
#pragma unroll
                for (int off = 1; off < 4; off <<= 1) {
                    unsigned long long o = __shfl_xor_sync(0xffffffffu, packed, off);
                    if (o < packed) packed = o;
                }
                if (t == 0) {
                    const int rl = wm * 32 + mf * 16 + g + half * 8;
                    red[rl * 2 + wn] = packed;
                }
            }
        }
        __syncthreads();
        if (tid < 128) {
            unsigned long long a = red[tid * 2], b = red[tid * 2 + 1];
            part[(size_t)(m0 + tid) * NSPL_ + blockIdx.x] = (a < b) ? a : b;
        }
    }
}

// ---------------- small kernels ----------------
__global__ void transpose_k(const float* __restrict__ src, float* __restrict__ dst, int R, int C)
{
    int e = blockIdx.x * 256 + threadIdx.x;
    if (e >= R * C) return;
    int rr = e / C, cc = e - rr * C;
    dst[(size_t)cc * R + rr] = src[e];
}

// conv_w [O][C][3][3] -> g_Wc [O][kk*512 + c]
__global__ void reorder_w(const float* __restrict__ cw, float* __restrict__ wc)
{
    int e = blockIdx.x * 256 + threadIdx.x;
    if (e >= ED_ * K2_) return;
    int o = e / K2_;
    int r = e - o * K2_;
    int kk = r >> 9;
    int c = r & 511;
    wc[e] = cw[(size_t)o * K2_ + c * 9 + kk];
}

// g_Y [B,256,512] -> g_col [4096][kk*512 + c]   (coalesced read & write)
__global__ void im2col_k(float* __restrict__ col)
{
    int e = blockIdx.x * 256 + threadIdx.x;
    if (e >= NROWS_ * K2_) return;
    int rr = e / K2_;
    int k2 = e - rr * K2_;
    int kk = k2 >> 9;
    int c = k2 & 511;
    int ky = kk / 3;
    int kx = kk - ky * 3;
    int b = rr >> 6, p = rr & 63;
    int h = p >> 3, w = p & 7;
    int gy = 2 * h - 1 + ky;
    int gx = 2 * w - 1 + kx;
    float v = 0.f;
    if ((unsigned)gy < 16u && (unsigned)gx < 16u)
        v = g_Y[(size_t)(b * 256 + gy * 16 + gx) * ED_ + c];
    col[e] = v;
}

// merge conv split-K halves: g_x = g_xs[0] + g_xs[1]
__global__ void add_k(const float* __restrict__ a, const float* __restrict__ b,
                      float* __restrict__ c)
{
    int e = blockIdx.x * 256 + threadIdx.x;       // float4 index
    float4 x = ((const float4*)a)[e];
    float4 y = ((const float4*)b)[e];
    x.x += y.x; x.y += y.y; x.z += y.z; x.w += y.w;
    ((float4*)c)[e] = x;
}

__global__ void cnorm_k(const float* __restrict__ Cb, float* __restrict__ cnp)
{
    int rr = blockIdx.x * 8 + (threadIdx.x >> 5);
    int lane = threadIdx.x & 31;
    const float* p = Cb + (size_t)rr * ED_;
    float s = 0.f;
    for (int i = lane; i < ED_; i += 32) { float v = p[i]; s = fmaf(v, v, s); }
#pragma unroll
    for (int off = 16; off > 0; off >>= 1) s += __shfl_down_sync(0xffffffffu, s, off);
    if (lane == 0) cnp[rr] = s;
}

__global__ void reduce_argmin(float* __restrict__ outIdxF, int writeIdx)
{
    int n = blockIdx.x * 256 + threadIdx.x;
    if (n >= NROWS_) return;
    unsigned long long best = ~0ull;
#pragma unroll 8
    for (int s = 0; s < NSPL_; ++s) {
        unsigned long long v = g_part[(size_t)n * NSPL_ + s];
        if (v < best) best = v;
    }
    int idx = (int)(unsigned)(best & 0xFFFFFFFFull);
    g_minidx[n] = idx;
    atomicAdd(&g_counts[idx], 1);
    if (writeIdx) outIdxF[n] = (float)idx;
}

// quantized = x + (||x-hard||/||rand|| + eps)*rand, written in decode-scrambled layout
__global__ void noise_k(const float* __restrict__ Cb, const float* __restrict__ rv)
{
    const int n = blockIdx.x;            // n = b*64 + p
    const int tid = threadIdx.x;         // 128 threads
    const int idx = g_minidx[n];
    const int b = n >> 6, p = n & 63;
    const float* xr = g_x + (size_t)n * ED_;
    const float* hr = Cb + (size_t)idx * ED_;
    const float* rr = rv + (size_t)n * ED_;

    float s1 = 0.f, s2 = 0.f;
    for (int i = tid; i < ED_; i += 128) {
        float d = xr[i] - hr[i];
        s1 = fmaf(d, d, s1);
        float rrr = rr[i];
        s2 = fmaf(rrr, rrr, s2);
    }
#pragma unroll
    for (int off = 16; off > 0; off >>= 1) {
        s1 += __shfl_down_sync(0xffffffffu, s1, off);
        s2 += __shfl_down_sync(0xffffffffu, s2, off);
    }
    __shared__ float sh1[4], sh2[4];
    int wid = tid >> 5, lane = tid & 31;
    if (lane == 0) { sh1[wid] = s1; sh2[wid] = s2; }
    __syncthreads();
    float t1 = sh1[0] + sh1[1] + sh1[2] + sh1[3];
    float t2 = sh2[0] + sh2[1] + sh2[2] + sh2[3];
    float scale = sqrtf(t1) / sqrtf(t2) + 1e-12f;
    for (int i = tid; i < ED_; i += 128) {
        float q = fmaf(scale, rr[i], xr[i]);
        // scrambled target: row m = b*64 + (i&63), col k = p*8 + (i>>6)
        g_Aq[(size_t)(b * 64 + (i & 63)) * ED_ + p * 8 + (i >> 6)] = q;
    }
}

__global__ void stats_k(float* __restrict__ d_out, int out_size)
{
    __shared__ float red[256];
    int tid = threadIdx.x;
    float s = 0.f;
    for (int i = tid; i < NE_; i += 256) {
        float c = (float)g_counts[i];
        float p = c * (1.f / (float)NROWS_);
        s += p * logf(p + 1e-12f);
        if (out_size > OFF_CB + i) d_out[OFF_CB + i] = c;
    }
    red[tid] = s;
    __syncthreads();
    for (int st = 128; st > 0; st >>= 1) {
        if (tid < st) red[tid] += red[tid + st];
        __syncthreads();
    }
    if (tid == 0 && out_size > OFF_PERP) d_out[OFF_PERP] = expf(-red[0]);
}

// ---------------- host launcher ----------------
extern "C" void kernel_launch(void* const* d_in, const int* in_sizes, int n_in,
                              void* d_out, int out_size)
{
    const float* first = (const float*)d_in[0];
    const float* last = (const float*)d_in[1];
    const float* W_in = (const float*)d_in[2];
    const float* conv_w = (const float*)d_in[4];
    const float* W_out = (const float*)d_in[6];
    const float* b_out = (const float*)d_in[7];
    const float* codebooks = (const float*)d_in[8];
    const float* randv = (const float*)d_in[9];
    float* out = (float*)d_out;

    float *pY, *pCol, *pWc, *pXs, *pX, *pAq, *pWinT, *pWoutT, *pCn;
    unsigned long long* pPart;
    int* pCnt;
    cudaGetSymbolAddress((void**)&pY, g_Y);
    cudaGetSymbolAddress((void**)&pCol, g_col);
    cudaGetSymbolAddress((void**)&pWc, g_Wc);
    cudaGetSymbolAddress((void**)&pXs, g_xs);
    cudaGetSymbolAddress((void**)&pX, g_x);
    cudaGetSymbolAddress((void**)&pAq, g_Aq);
    cudaGetSymbolAddress((void**)&pWinT, g_WinT);
    cudaGetSymbolAddress((void**)&pWoutT, g_WoutT);
    cudaGetSymbolAddress((void**)&pCn, g_cnorm);
    cudaGetSymbolAddress((void**)&pPart, g_part);
    cudaGetSymbolAddress((void**)&pCnt, g_counts);

    cudaFuncSetAttribute(mm_gemm<0, 0>, cudaFuncAttributeMaxDynamicSharedMemorySize, SMEM_BYTES);
    cudaFuncSetAttribute(mm_gemm<1, 0>, cudaFuncAttributeMaxDynamicSharedMemorySize, SMEM_BYTES);
    cudaFuncSetAttribute(mm_gemm<1, 1>, cudaFuncAttributeMaxDynamicSharedMemorySize, SMEM_BYTES);
    cudaFuncSetAttribute(mm_gemm<1, 2>, cudaFuncAttributeMaxDynamicSharedMemorySize, SMEM_BYTES);

    cudaMemsetAsync(pCnt, 0, NE_ * sizeof(int));

    // weight preps
    transpose_k<<<(DIM_ * ED_ + 255) / 256, 256>>>(W_in, pWinT, DIM_, ED_);
    transpose_k<<<(ED_ * DIM_ + 255) / 256, 256>>>(W_out, pWoutT, ED_, DIM_);
    reorder_w<<<(ED_ * K2_ + 255) / 256, 256>>>(conv_w, pWc);

    // 1. projection: (last-first)[16384,1024] @ W_in -> g_Y [16384,512]
    mm_gemm<0, 0><<<dim3(4, 128, 1), 256, SMEM_BYTES>>>(
        last, first, pWinT, nullptr, nullptr, pY, nullptr, DIM_, DIM_, DIM_, ED_, 0);
    // 2. im2col
    im2col_k<<<((size_t)NROWS_ * K2_ + 255) / 256, 256>>>(pCol);
    // 3. conv GEMM, split-K x2 (grid.z): col [4096,4608] @ g_Wc^T -> g_xs halves
    mm_gemm<1, 0><<<dim3(4, 32, 2), 256, SMEM_BYTES>>>(
        pCol, nullptr, pWc, nullptr, nullptr, pXs, nullptr,
        K2_ / 2, K2_, K2_, ED_, (size_t)NROWS_ * ED_);
    // 3b. merge halves -> g_x
    add_k<<<(NROWS_ * ED_ / 4) / 256, 256>>>(pXs, pXs + (size_t)NROWS_ * ED_, pX);
    // 4. codebook norms
    cnorm_k<<<NE_ / 8, 256>>>(codebooks, pCn);
    // 5. distance GEMM + fused argmin partials
    mm_gemm<1, 2><<<dim3(NSPL_, 32, 1), 256, SMEM_BYTES>>>(
        pX, nullptr, codebooks, nullptr, pCn, nullptr, pPart, ED_, ED_, ED_, 0, 0);
    // 6. reduce + histogram + min_indices
    int writeIdx = (out_size >= OFF_IDX + NROWS_) ? 1 : 0;
    reduce_argmin<<<NROWS_ / 256, 256>>>(out + OFF_IDX, writeIdx);
    // 7. noise substitution -> scrambled g_Aq
    noise_k<<<NROWS_, 128>>>(codebooks, randv);
    // 8. decode: g_Aq [4096,512] @ W_out + b_out -> out [4096,1024]
    mm_gemm<1, 1><<<dim3(8, 32, 1), 256, SMEM_BYTES>>>(
        pAq, nullptr, pWoutT, b_out, nullptr, out, nullptr, ED_, ED_, ED_, DIM_, 0);
    // 9. perplexity + codebooks_used
    stats_k<<<1, 256>>>(out, out_size);
}